// round 5
// baseline (speedup 1.0000x reference)
#include <cuda_runtime.h>
#include <cstdint>
#include <cstddef>

#define BB 64
#define VV 2048
#define HH 128
#define NNODE (BB*VV)      /* 131072 */
#define EE 1048576
#define CFD 47
#define EPSB 1e-5f
#define TS 136             /* smem row stride: conflict-free fragment loads */

// ---------------- device scratch (allocation-free rule) ----------------
__device__ __align__(16) float g_Y1e[(size_t)EE*HH];      // 512MB  X@w1+b1 (pre-BN)
__device__ __align__(16) float g_H2[(size_t)EE*2*HH];     // 1GB    silu(BN1)@w2+b2 (pre-BN)
__device__ __align__(16) float g_h[(size_t)NNODE*HH];     // 64MB
__device__ __align__(16) float g_hprop[(size_t)NNODE*HH];
__device__ __align__(16) float g_y1[(size_t)NNODE*HH];
__device__ __align__(16) float g_y2[(size_t)NNODE*HH];
__device__ __align__(16) float g_hspec[(size_t)BB*HH*HH]; // 4MB
__device__ float g_stsum[2*HH];
__device__ float g_stsq[2*HH];
__device__ float g_affA[2*HH];
__device__ float g_affC[2*HH];
__device__ float g_outacc[BB];

__device__ __forceinline__ float siluf(float x){ return x/(1.f+__expf(-x)); }

__device__ __forceinline__ float tf32r(float x){
    unsigned r; asm("cvt.rna.tf32.f32 %0, %1;" : "=r"(r) : "f"(x));
    return __uint_as_float(r);
}

__device__ __forceinline__ void mma8(float* c, const unsigned* a, const unsigned* b){
    asm volatile("mma.sync.aligned.m16n8k8.row.col.f32.tf32.tf32.f32 "
        "{%0,%1,%2,%3}, {%4,%5,%6,%7}, {%8,%9}, {%0,%1,%2,%3};"
        : "+f"(c[0]), "+f"(c[1]), "+f"(c[2]), "+f"(c[3])
        : "r"(a[0]), "r"(a[1]), "r"(a[2]), "r"(a[3]), "r"(b[0]), "r"(b[1]));
}

// one 16-deep K-tile of warp MMAs: warp computes 64x32 of the 128x128 block tile
__device__ __forceinline__ void mma_ktile(const float* As, const float* Bs,
                                          float (&acc)[4][4][4],
                                          int wr,int wc,int gid,int tq){
    #pragma unroll
    for(int kb=0;kb<16;kb+=8){
        unsigned a[4][4], b[4][2];
        #pragma unroll
        for(int mt=0;mt<4;mt++){
            int row=wr*64+mt*16+gid;
            a[mt][0]=__float_as_uint(As[(kb+tq)*TS+row]);
            a[mt][1]=__float_as_uint(As[(kb+tq)*TS+row+8]);
            a[mt][2]=__float_as_uint(As[(kb+tq+4)*TS+row]);
            a[mt][3]=__float_as_uint(As[(kb+tq+4)*TS+row+8]);
        }
        #pragma unroll
        for(int nt=0;nt<4;nt++){
            int col=wc*32+nt*8+gid;
            b[nt][0]=__float_as_uint(Bs[(kb+tq)*TS+col]);
            b[nt][1]=__float_as_uint(Bs[(kb+tq+4)*TS+col]);
        }
        #pragma unroll
        for(int mt=0;mt<4;mt++)
            #pragma unroll
            for(int nt=0;nt<4;nt++)
                mma8(acc[mt][nt], a[mt], b[nt]);
    }
}

// ---------------- zero kernels ----------------
__global__ void k_zero_h(){
    size_t i=(size_t)blockIdx.x*blockDim.x+threadIdx.x;
    ((float4*)g_h)[i]=make_float4(0.f,0.f,0.f,0.f);
    if(blockIdx.x==0&&threadIdx.x<BB) g_outacc[threadIdx.x]=0.f;
}
__global__ void k_zero_spec(){
    size_t i=(size_t)blockIdx.x*blockDim.x+threadIdx.x;
    ((float4*)g_hspec)[i]=make_float4(0.f,0.f,0.f,0.f);
}
__global__ void k_zero_st(){
    int t=threadIdx.x;
    if(t<2*HH){ g_stsum[t]=0.f; g_stsq[t]=0.f; }
}

// ---------------- fold stats -> affine ----------------
__global__ void k_fold(int ncols, float invn,
                       const float* __restrict__ g, const float* __restrict__ be){
    int j=threadIdx.x;
    if(j<ncols){
        float m=g_stsum[j]*invn;
        float var=g_stsq[j]*invn-m*m;
        float A=g[j]*rsqrtf(var+EPSB);
        g_affA[j]=A;
        g_affC[j]=be[j]-A*m;
    }
}

// ---------------- GEMM1 (tf32 MMA): Y1 = X@w1 + b1, K=47 padded to 48 ----------------
__global__ __launch_bounds__(256) void k_gemm1(const float* __restrict__ X,
                                               const float* __restrict__ w1,
                                               const float* __restrict__ b1){
    __shared__ float As[16*TS];
    __shared__ float Bs[16*TS];
    __shared__ float ssum[128], ssq[128];
    int t=threadIdx.x;
    int w=t>>5, lane=t&31;
    int wr=w&1, wc=w>>1, gid=lane>>2, tq=lane&3;
    size_t m0=(size_t)blockIdx.x*128;
    float acc[4][4][4]={};
    int am=t>>1, akq=(t&1)*8;
    int bk=t>>4, bn=(t&15)*8;
    for(int k0=0;k0<48;k0+=16){
        #pragma unroll
        for(int i=0;i<8;i++){
            int k=k0+akq+i;
            As[(akq+i)*TS+am] = (k<CFD)? tf32r(X[(m0+am)*CFD+k]) : 0.f;
        }
        int kb=k0+bk;
        #pragma unroll
        for(int j=0;j<8;j++)
            Bs[bk*TS+bn+j] = (kb<CFD)? tf32r(w1[(size_t)kb*HH+bn+j]) : 0.f;
        __syncthreads();
        mma_ktile(As,Bs,acc,wr,wc,gid,tq);
        __syncthreads();
    }
    if(t<128){ ssum[t]=0.f; ssq[t]=0.f; }
    __syncthreads();
    #pragma unroll
    for(int mt=0;mt<4;mt++){
        size_t row0=m0+wr*64+mt*16+gid;
        #pragma unroll
        for(int nt=0;nt<4;nt++){
            int cl=wc*32+nt*8+tq*2;
            float b0=b1[cl], b1v=b1[cl+1];
            float v0=acc[mt][nt][0]+b0, v1=acc[mt][nt][1]+b1v;
            float v2=acc[mt][nt][2]+b0, v3=acc[mt][nt][3]+b1v;
            *(float2*)&g_Y1e[row0*HH+cl]     = make_float2(v0,v1);
            *(float2*)&g_Y1e[(row0+8)*HH+cl] = make_float2(v2,v3);
            atomicAdd(&ssum[cl],  v0+v2); atomicAdd(&ssq[cl],  v0*v0+v2*v2);
            atomicAdd(&ssum[cl+1],v1+v3); atomicAdd(&ssq[cl+1],v1*v1+v3*v3);
        }
    }
    __syncthreads();
    if(t<128){ atomicAdd(&g_stsum[t],ssum[t]); atomicAdd(&g_stsq[t],ssq[t]); }
}

// ---------------- generic 128x128 tiled GEMM (tf32 MMA) ----------------
// mode 0: plain A   mode 1: A=concat(g_h,g_hprop), Kdim=256
// mode 2: A elem -> silu(affA*a+affC)   mode 3: A=evecs (per-batch), B=g_hspec
// asel: 0=g_Y1e 1=g_h 2=g_y1 ; csel: 0=g_H2 1=g_hprop 2=g_y1 3=g_y2
__global__ __launch_bounds__(256) void k_mm(int mode, int asel, int csel,
        const float* __restrict__ eigs,
        const float* __restrict__ Bw, int ldb,
        const float* __restrict__ bias,
        int ldc, int Kdim, int do_stats)
{
    __shared__ float As[16*TS];
    __shared__ float Bs[16*TS];
    __shared__ float ssum[128], ssq[128];
    const float* A=(asel==0)?g_Y1e:(asel==1)?g_h:g_y1;
    float* Cout=(csel==0)?g_H2:(csel==1)?g_hprop:(csel==2)?g_y1:g_y2;
    int t=threadIdx.x;
    int w=t>>5, lane=t&31;
    int wr=w&1, wc=w>>1, gid=lane>>2, tq=lane&3;
    size_t m0=(size_t)blockIdx.x*128;
    int bcol=blockIdx.y*128;
    const float* Abase=A;
    const float* Bbase=Bw;
    if(mode==3){
        size_t b=m0>>11;
        Abase=eigs+(b*4097+1)*128+(m0&2047)*128;
        Bbase=g_hspec+b*16384;
    }
    float acc[4][4][4]={};
    int am=t>>1, akq=(t&1)*8;
    int bk=t>>4, bn=(t&15)*8;
    for(int k0=0;k0<Kdim;k0+=16){
        const float* ap;
        if(mode==1) ap=(k0<128)?(g_h+(m0+am)*128+k0+akq):(g_hprop+(m0+am)*128+(k0-128)+akq);
        else if(mode==3) ap=Abase+(size_t)am*128+k0+akq;
        else ap=Abase+(m0+am)*128+k0+akq;
        float4 v0=*(const float4*)ap, v1=*(const float4*)(ap+4);
        float av[8]={v0.x,v0.y,v0.z,v0.w,v1.x,v1.y,v1.z,v1.w};
        if(mode==2){
            #pragma unroll
            for(int i=0;i<8;i++){ int kg=k0+akq+i; av[i]=siluf(g_affA[kg]*av[i]+g_affC[kg]); }
        }
        #pragma unroll
        for(int i=0;i<8;i++) As[(akq+i)*TS+am]=tf32r(av[i]);
        const float* bp=Bbase+(size_t)(k0+bk)*ldb+bcol+bn;
        float4 b0=*(const float4*)bp, b1v=*(const float4*)(bp+4);
        Bs[bk*TS+bn+0]=tf32r(b0.x); Bs[bk*TS+bn+1]=tf32r(b0.y);
        Bs[bk*TS+bn+2]=tf32r(b0.z); Bs[bk*TS+bn+3]=tf32r(b0.w);
        Bs[bk*TS+bn+4]=tf32r(b1v.x); Bs[bk*TS+bn+5]=tf32r(b1v.y);
        Bs[bk*TS+bn+6]=tf32r(b1v.z); Bs[bk*TS+bn+7]=tf32r(b1v.w);
        __syncthreads();
        mma_ktile(As,Bs,acc,wr,wc,gid,tq);
        __syncthreads();
    }
    if(do_stats){ if(t<128){ ssum[t]=0.f; ssq[t]=0.f; } __syncthreads(); }
    #pragma unroll
    for(int mt=0;mt<4;mt++){
        size_t row0=m0+wr*64+mt*16+gid;
        #pragma unroll
        for(int nt=0;nt<4;nt++){
            int cl=wc*32+nt*8+tq*2;
            float bb0=bias?bias[bcol+cl]:0.f, bb1=bias?bias[bcol+cl+1]:0.f;
            float v0=acc[mt][nt][0]+bb0, v1=acc[mt][nt][1]+bb1;
            float v2=acc[mt][nt][2]+bb0, v3=acc[mt][nt][3]+bb1;
            *(float2*)&Cout[row0*(size_t)ldc+bcol+cl]     = make_float2(v0,v1);
            *(float2*)&Cout[(row0+8)*(size_t)ldc+bcol+cl] = make_float2(v2,v3);
            if(do_stats){
                atomicAdd(&ssum[cl],  v0+v2); atomicAdd(&ssq[cl],  v0*v0+v2*v2);
                atomicAdd(&ssum[cl+1],v1+v3); atomicAdd(&ssq[cl+1],v1*v1+v3*v3);
            }
        }
    }
    if(do_stats){
        __syncthreads();
        if(t<128){ atomicAdd(&g_stsum[bcol+t],ssum[t]); atomicAdd(&g_stsq[bcol+t],ssq[t]); }
    }
}

// ---------------- msg activation + segment-sum scatter ----------------
__global__ __launch_bounds__(256) void k_msg(const int* __restrict__ nbr){
    int warp=threadIdx.x>>5, lane=threadIdx.x&31;
    size_t e=(size_t)blockIdx.x*8+warp;
    const float* h2=g_H2+e*256;
    int j=lane*4;
    float4 f=*(const float4*)(h2+j);
    float4 c=*(const float4*)(h2+128+j);
    float fr[4]={f.x,f.y,f.z,f.w}, cr[4]={c.x,c.y,c.z,c.w}, o[4];
    #pragma unroll
    for(int s=0;s<4;s++){
        int jj=j+s;
        float fv=g_affA[jj]*fr[s]+g_affC[jj];
        float cv=g_affA[128+jj]*cr[s]+g_affC[128+jj];
        float sg=1.f/(1.f+__expf(-fv));
        float sp=fmaxf(cv,0.f)+log1pf(__expf(-fabsf(cv)));
        o[s]=sg*sp;
    }
    float* dst=g_h+(size_t)nbr[e]*128+j;
    atomicAdd(dst+0,o[0]); atomicAdd(dst+1,o[1]);
    atomicAdd(dst+2,o[2]); atomicAdd(dst+3,o[3]);
}

// ---------------- h_spec (tf32 MMA): per-batch Einv^T @ hb, V chunked x4 ----------------
__global__ __launch_bounds__(256) void k_spec(const float* __restrict__ eigs){
    __shared__ float As[16*TS];
    __shared__ float Bs[16*TS];
    int t=threadIdx.x;
    int w=t>>5, lane=t&31;
    int wr=w&1, wc=w>>1, gid=lane>>2, tq=lane&3;
    int b=blockIdx.x>>2, c=blockIdx.x&3;
    int v0=c*512;
    const float* Abase=eigs+((size_t)b*4097+1+2048)*128;   // evecs_inv rows [v][128]
    const float* Hbase=g_h+((size_t)b*2048)*128;
    int vr=t>>4, cq=(t&15)*8;
    float acc[4][4][4]={};
    for(int vt=0;vt<512;vt+=16){
        const float* ap=Abase+(size_t)(v0+vt+vr)*128+cq;
        float4 a0=*(const float4*)ap, a1=*(const float4*)(ap+4);
        As[vr*TS+cq+0]=tf32r(a0.x); As[vr*TS+cq+1]=tf32r(a0.y);
        As[vr*TS+cq+2]=tf32r(a0.z); As[vr*TS+cq+3]=tf32r(a0.w);
        As[vr*TS+cq+4]=tf32r(a1.x); As[vr*TS+cq+5]=tf32r(a1.y);
        As[vr*TS+cq+6]=tf32r(a1.z); As[vr*TS+cq+7]=tf32r(a1.w);
        const float* bp=Hbase+(size_t)(v0+vt+vr)*128+cq;
        float4 b0=*(const float4*)bp, b1v=*(const float4*)(bp+4);
        Bs[vr*TS+cq+0]=tf32r(b0.x); Bs[vr*TS+cq+1]=tf32r(b0.y);
        Bs[vr*TS+cq+2]=tf32r(b0.z); Bs[vr*TS+cq+3]=tf32r(b0.w);
        Bs[vr*TS+cq+4]=tf32r(b1v.x); Bs[vr*TS+cq+5]=tf32r(b1v.y);
        Bs[vr*TS+cq+6]=tf32r(b1v.z); Bs[vr*TS+cq+7]=tf32r(b1v.w);
        __syncthreads();
        mma_ktile(As,Bs,acc,wr,wc,gid,tq);
        __syncthreads();
    }
    float* dst=g_hspec+(size_t)b*16384;
    #pragma unroll
    for(int mt=0;mt<4;mt++){
        int row0=wr*64+mt*16+gid;
        #pragma unroll
        for(int nt=0;nt<4;nt++){
            int cl=wc*32+nt*8+tq*2;
            atomicAdd(&dst[row0*128+cl],    acc[mt][nt][0]);
            atomicAdd(&dst[row0*128+cl+1],  acc[mt][nt][1]);
            atomicAdd(&dst[(row0+8)*128+cl],  acc[mt][nt][2]);
            atomicAdd(&dst[(row0+8)*128+cl+1],acc[mt][nt][3]);
        }
    }
}

// ---------------- h_spec *= exp(-lam*t) ----------------
__global__ void k_coeff(const float* __restrict__ eigs, const float* __restrict__ pt){
    int i=blockIdx.x*blockDim.x+threadIdx.x;   // B*128*128
    int b=i>>14, k=(i>>7)&127, hcol=i&127;
    float lam=eigs[(size_t)b*4097*128+k];
    float tt=fmaxf(pt[hcol],1e-6f);
    g_hspec[i]*=__expf(-lam*tt);
}

// ---------------- h += affA*y2 + affC ----------------
__global__ void k_update(){
    size_t i=(size_t)blockIdx.x*blockDim.x+threadIdx.x;
    int j=(int)((i*4)&127);
    float4 y=((const float4*)g_y2)[i];
    float4 h=((float4*)g_h)[i];
    h.x+=g_affA[j+0]*y.x+g_affC[j+0];
    h.y+=g_affA[j+1]*y.y+g_affC[j+1];
    h.z+=g_affA[j+2]*y.z+g_affC[j+2];
    h.w+=g_affA[j+3]*y.w+g_affC[j+3];
    ((float4*)g_h)[i]=h;
}

// ---------------- final projection + mean over V ----------------
__global__ __launch_bounds__(256) void k_out(const float* __restrict__ wo2){
    __shared__ float part[8];
    int warp=threadIdx.x>>5, lane=threadIdx.x&31;
    size_t row=(size_t)blockIdx.x*8+warp;
    int j=lane*4;
    float4 y=*(const float4*)&g_y1[row*128+j];
    float4 w=*(const float4*)&wo2[j];
    float v=0.f;
    v+=siluf(g_affA[j+0]*y.x+g_affC[j+0])*w.x;
    v+=siluf(g_affA[j+1]*y.y+g_affC[j+1])*w.y;
    v+=siluf(g_affA[j+2]*y.z+g_affC[j+2])*w.z;
    v+=siluf(g_affA[j+3]*y.w+g_affC[j+3])*w.w;
    #pragma unroll
    for(int s=16;s>0;s>>=1) v+=__shfl_xor_sync(0xffffffffu,v,s);
    if(lane==0) part[warp]=v;
    __syncthreads();
    if(threadIdx.x==0){
        float s=0.f;
        #pragma unroll
        for(int q=0;q<8;q++) s+=part[q];
        atomicAdd(&g_outacc[blockIdx.x>>8],s);   // 256 blocks per batch
    }
}

__global__ void k_final(float* out, const float* __restrict__ bo2){
    int b=threadIdx.x;
    if(b<BB) out[b]=g_outacc[b]*(1.f/(float)VV)+bo2[0];
}

// ---------------- launch ----------------
extern "C" void kernel_launch(void* const* d_in, const int* in_sizes, int n_in,
                              void* d_out, int out_size){
    const float* chem =(const float*)d_in[0];
    const int*   nbr  =(const int*)  d_in[1];
    const float* eigs =(const float*)d_in[2];
    const float* w1   =(const float*)d_in[3];
    const float* b1   =(const float*)d_in[4];
    const float* g1   =(const float*)d_in[5];
    const float* be1  =(const float*)d_in[6];
    const float* w2   =(const float*)d_in[7];
    const float* b2   =(const float*)d_in[8];
    const float* g2   =(const float*)d_in[9];
    const float* be2  =(const float*)d_in[10];
    const float* prop =(const float*)d_in[11];
    const float* pw1  =(const float*)d_in[12];
    const float* pb1  =(const float*)d_in[13];
    const float* pg1  =(const float*)d_in[14];
    const float* pbe1 =(const float*)d_in[15];
    const float* pw2  =(const float*)d_in[16];
    const float* pb2  =(const float*)d_in[17];
    const float* pg2  =(const float*)d_in[18];
    const float* pbe2 =(const float*)d_in[19];
    const float* wo1  =(const float*)d_in[20];
    const float* bo1  =(const float*)d_in[21];
    const float* go1  =(const float*)d_in[22];
    const float* beo1 =(const float*)d_in[23];
    const float* wo2  =(const float*)d_in[24];
    const float* bo2  =(const float*)d_in[25];
    (void)in_sizes; (void)n_in; (void)out_size;

    // chem MLP over E rows
    k_zero_h<<<4096,1024>>>();
    k_zero_st<<<1,256>>>();
    k_gemm1<<<EE/128,256>>>(chem,w1,b1);
    k_fold<<<1,256>>>(128,1.f/(float)EE,g1,be1);
    k_zero_st<<<1,256>>>();
    k_mm<<<dim3(EE/128,2),256>>>(2,0,0,nullptr,w2,256,b2,256,128,1);   // H2 = siluBN1(Y1)@w2+b2
    k_fold<<<1,256>>>(256,1.f/(float)EE,g2,be2);
    k_msg<<<EE/8,256>>>(nbr);                                          // h = segment_sum(msg)

    // propagation layers
    for(int l=0;l<3;l++){
        k_zero_spec<<<256,1024>>>();
        k_spec<<<256,256>>>(eigs);
        k_coeff<<<4096,256>>>(eigs,prop+l*128);
        k_mm<<<dim3(NNODE/128,1),256>>>(3,1,1,eigs,nullptr,128,nullptr,128,128,0);  // h_prop
        k_zero_st<<<1,256>>>();
        k_mm<<<dim3(NNODE/128,1),256>>>(1,1,2,nullptr,pw1+(size_t)l*256*128,128,pb1+l*128,128,256,1); // y1
        k_fold<<<1,256>>>(128,1.f/(float)NNODE,pg1+l*128,pbe1+l*128);
        k_zero_st<<<1,256>>>();
        k_mm<<<dim3(NNODE/128,1),256>>>(2,2,3,nullptr,pw2+(size_t)l*128*128,128,pb2+l*128,128,128,1); // y2
        k_fold<<<1,256>>>(128,1.f/(float)NNODE,pg2+l*128,pbe2+l*128);
        k_update<<<16384,256>>>();                                     // h += BN(y2)
    }

    // output head
    k_zero_st<<<1,256>>>();
    k_mm<<<dim3(NNODE/128,1),256>>>(0,1,2,nullptr,wo1,128,bo1,128,128,1);  // y1 = h@wo1+bo1
    k_fold<<<1,256>>>(128,1.f/(float)NNODE,go1,beo1);
    k_out<<<NNODE/8,256>>>(wo2);
    k_final<<<1,64>>>((float*)d_out,bo2);
}

// round 8
// speedup vs baseline: 1.0317x; 1.0317x over previous
#include <cuda_runtime.h>
#include <cstdint>
#include <cstddef>

#define BB 64
#define VV 2048
#define HH 128
#define NNODE (BB*VV)      /* 131072 */
#define EE 1048576
#define CFD 47
#define EPSB 1e-5f

// ---------------- device scratch (allocation-free rule) ----------------
__device__ __align__(16) float g_Y1e[(size_t)EE*HH];       // 512MB
__device__ __align__(16) float g_H2[(size_t)EE*2*HH];      // 1GB
__device__ __align__(16) float g_chem48[(size_t)EE*48];    // 192MB tf32-rounded, padded
__device__ __align__(16) float g_h[(size_t)NNODE*HH];
__device__ __align__(16) float g_hprop[(size_t)NNODE*HH];
__device__ __align__(16) float g_y1[(size_t)NNODE*HH];
__device__ __align__(16) float g_y2[(size_t)NNODE*HH];
__device__ __align__(16) float g_hspec[(size_t)BB*HH*HH];
__device__ __align__(16) float g_hbT[(size_t)BB*HH*VV];
__device__ __align__(16) float g_einvT[(size_t)BB*HH*VV];
__device__ __align__(16) float g_evr[(size_t)NNODE*HH];
__device__ __align__(16) float g_w1T[128*48];
__device__ __align__(16) float g_w2T[256*128];
__device__ __align__(16) float g_pw1T[3*128*256];
__device__ __align__(16) float g_pw2T[3*128*128];
__device__ __align__(16) float g_wo1T[128*128];
__device__ float g_stsum[2*HH];
__device__ float g_stsq[2*HH];
__device__ float g_affA[2*HH];
__device__ float g_affC[2*HH];
__device__ float g_outacc[BB];

__device__ __forceinline__ float siluf(float x){ return x/(1.f+__expf(-x)); }
__device__ __forceinline__ float tf32r(float x){
    unsigned r; asm("cvt.rna.tf32.f32 %0, %1;" : "=r"(r) : "f"(x));
    return __uint_as_float(r);
}
__device__ __forceinline__ uint32_t cvsmem(const void* p){
    uint32_t a;
    asm("{ .reg .u64 t; cvta.to.shared.u64 t, %1; cvt.u32.u64 %0, t; }" : "=r"(a) : "l"(p));
    return a;
}
__device__ __forceinline__ void cpa16(uint32_t dst, const void* src){
    asm volatile("cp.async.ca.shared.global [%0], [%1], 16;" :: "r"(dst), "l"(src));
}
#define CPCOMMIT() asm volatile("cp.async.commit_group;" ::: "memory")
#define CPWAIT1()  asm volatile("cp.async.wait_group 1;" ::: "memory")
#define CPWAIT0()  asm volatile("cp.async.wait_group 0;" ::: "memory")

__device__ __forceinline__ void ldsm4(uint32_t& r0,uint32_t& r1,uint32_t& r2,uint32_t& r3,uint32_t a){
    asm volatile("ldmatrix.sync.aligned.m8n8.x4.shared.b16 {%0,%1,%2,%3}, [%4];"
                 : "=r"(r0),"=r"(r1),"=r"(r2),"=r"(r3) : "r"(a));
}
__device__ __forceinline__ void mma8(float* c, const uint32_t* a, const uint32_t* b){
    asm volatile("mma.sync.aligned.m16n8k8.row.col.f32.tf32.tf32.f32 "
        "{%0,%1,%2,%3}, {%4,%5,%6,%7}, {%8,%9}, {%0,%1,%2,%3};"
        : "+f"(c[0]), "+f"(c[1]), "+f"(c[2]), "+f"(c[3])
        : "r"(a[0]), "r"(a[1]), "r"(a[2]), "r"(a[3]), "r"(b[0]), "r"(b[1]));
}

// ---------------- zero / fold ----------------
__global__ void k_zero_h(){
    size_t i=(size_t)blockIdx.x*blockDim.x+threadIdx.x;
    ((float4*)g_h)[i]=make_float4(0.f,0.f,0.f,0.f);
    if(blockIdx.x==0&&threadIdx.x<BB) g_outacc[threadIdx.x]=0.f;
}
__global__ void k_zero_st(){
    int t=threadIdx.x;
    if(t<2*HH){ g_stsum[t]=0.f; g_stsq[t]=0.f; }
}
__global__ void k_fold(int ncols, float invn,
                       const float* __restrict__ g, const float* __restrict__ be){
    int j=threadIdx.x;
    if(j<ncols){
        float m=g_stsum[j]*invn;
        float var=g_stsq[j]*invn-m*m;
        float A=g[j]*rsqrtf(var+EPSB);
        g_affA[j]=A;
        g_affC[j]=be[j]-A*m;
    }
}

// ---------------- prep passes (one-time) ----------------
// weight transpose+round: dst[n*ldd+k] = tf32r(src[k*N+n]), zero-pad k>=K
__global__ void k_wt(float* dst, const float* __restrict__ src, int K, int N, int ldd){
    int i=blockIdx.x*256+threadIdx.x;
    if(i>=N*ldd) return;
    int n=i/ldd, k=i-n*ldd;
    dst[i]=(k<K)? tf32r(src[(size_t)k*N+n]) : 0.f;
}
// chem -> padded [E][48], rounded. warp per row.
__global__ void k_prep(const float* __restrict__ X){
    int wp=threadIdx.x>>5, lane=threadIdx.x&31;
    size_t r=(size_t)blockIdx.x*8+wp;
    float v=X[r*CFD+lane];
    g_chem48[r*48+lane]=tf32r(v);
    if(lane<16){
        int c=32+lane;
        float v2=(c<CFD)? X[r*CFD+c] : 0.f;
        g_chem48[r*48+c]=(c<CFD)? tf32r(v2) : 0.f;
    }
}
// evecs copy rounded: g_evr[n][k]
__global__ void k_evr(const float* __restrict__ eigs){
    size_t i=(size_t)blockIdx.x*blockDim.x+threadIdx.x;
    size_t n=(i*4)>>7; int k=(int)((i*4)&127);
    size_t b=n>>11, v=n&2047;
    float4 x=*(const float4*)(eigs+((b*4097)+1+v)*128+k);
    x.x=tf32r(x.x); x.y=tf32r(x.y); x.z=tf32r(x.z); x.w=tf32r(x.w);
    ((float4*)g_evr)[i]=x;
}
// evecs_inv transpose rounded: g_einvT[b][k][v]
__global__ void k_einvT(const float* __restrict__ eigs){
    __shared__ float tile[32][33];
    int b=blockIdx.z;
    int v0=blockIdx.x*32, k0=blockIdx.y*32;
    int tx=threadIdx.x, ty=threadIdx.y;
    #pragma unroll
    for(int i=0;i<32;i+=8)
        tile[ty+i][tx]=eigs[((size_t)b*4097+1+2048+v0+ty+i)*128 + k0+tx];
    __syncthreads();
    #pragma unroll
    for(int i=0;i<32;i+=8)
        g_einvT[((size_t)b*128 + k0+ty+i)*2048 + v0+tx]=tf32r(tile[tx][ty+i]);
}
// h transpose (rounded) + round h in place
__global__ void k_hbT(){
    __shared__ float tile[32][33];
    int b=blockIdx.z;
    int v0=blockIdx.x*32, h0=blockIdx.y*32;
    int tx=threadIdx.x, ty=threadIdx.y;
    #pragma unroll
    for(int i=0;i<32;i+=8){
        size_t idx=((size_t)b*2048+v0+ty+i)*128 + h0+tx;
        float v=g_h[idx];
        float rv=tf32r(v);
        tile[ty+i][tx]=rv;
        g_h[idx]=rv;
    }
    __syncthreads();
    #pragma unroll
    for(int i=0;i<32;i+=8)
        g_hbT[((size_t)b*128 + h0+ty+i)*2048 + v0+tx]=tile[tx][ty+i];
}
// in-place y = tf32r(silu(affA*y+affC)), 128-col rows
__global__ void k_act(float* y){
    size_t i=(size_t)blockIdx.x*blockDim.x+threadIdx.x;
    int j=(int)((i*4)&127);
    float4 v=((const float4*)y)[i];
    v.x=tf32r(siluf(g_affA[j+0]*v.x+g_affC[j+0]));
    v.y=tf32r(siluf(g_affA[j+1]*v.y+g_affC[j+1]));
    v.z=tf32r(siluf(g_affA[j+2]*v.z+g_affC[j+2]));
    v.w=tf32r(siluf(g_affA[j+3]*v.w+g_affC[j+3]));
    ((float4*)y)[i]=v;
}

// ---------------- tf32 mma.sync GEMM: C[128x128] = A(Mx K) * B(N x K)^T ----------------
// amode: 0 plain (lda), 1 concat(g_h|g_hprop)
// bmode: 0 weights (bcol, ldb), 1 hspec per batch (m0>>11), 2 einvT per batch
// epi: bit0 stats, bit1 coeff exp(-lam[col]*t[row]), bit2 round output
__global__ __launch_bounds__(256,2) void k_tc(
    int amode, const float* __restrict__ A, int lda,
    int bmode, const float* __restrict__ B, int ldb,
    float* __restrict__ C, int ldc, const float* __restrict__ bias,
    int nc, int epi, const float* __restrict__ eigs, const float* __restrict__ pt)
{
    __shared__ float sm[2*2*128*20];       // [stage][A|B][128 rows][20 words]
    __shared__ float ssum[128], ssq[128];
    int t=threadIdx.x, w=t>>5, lane=t&31;
    int wr=w&1, wc=w>>1, gid=lane>>2, tq=lane&3;
    size_t m0=(size_t)blockIdx.x*128;
    int bcol=blockIdx.y*128;
    uint32_t sbase=cvsmem(sm);

    auto fill=[&](int c){
        int st=c&1; int k0=c*16;
        uint32_t abase=sbase + st*20480u;
        uint32_t bbase=abase + 10240u;
        #pragma unroll
        for(int q=0;q<2;q++){
            int i=t+q*256;
            int row=i>>2, seg=i&3, kg=k0+seg*4;
            const float* sa;
            if(amode==1) sa=(kg<128)? (g_h+(m0+row)*128+kg) : (g_hprop+(m0+row)*128+(kg-128));
            else         sa=A+(m0+row)*(size_t)lda+kg;
            cpa16(abase + (uint32_t)(row*80+seg*16), sa);
            const float* sb;
            if(bmode==0)      sb=B + (size_t)(bcol+row)*ldb + kg;
            else if(bmode==1) sb=B + (size_t)(m0>>11)*16384 + (size_t)row*128 + kg;
            else              sb=B + (size_t)m0*2048 + (size_t)row*2048 + kg;
            cpa16(bbase + (uint32_t)(row*80+seg*16), sb);
        }
    };

    int arow=(lane&7)+((lane>>3)&1)*8;
    int akq=((lane>>4)&1)*4;
    int brow=(lane&7)+((lane>>4)&1)*8;
    int bkq=((lane>>3)&1)*4;

    float acc[4][4][4]={};
    fill(0); CPCOMMIT();
    for(int c=0;c<nc;c++){
        if(c+1<nc){ fill(c+1); CPCOMMIT(); CPWAIT1(); }
        else      { CPWAIT0(); }
        __syncthreads();
        int st=c&1;
        uint32_t abase=sbase + st*20480u;
        uint32_t bbase=abase + 10240u;
        #pragma unroll
        for(int s=0;s<2;s++){
            uint32_t a[4][4];
            #pragma unroll
            for(int mt=0;mt<4;mt++){
                uint32_t ad=abase + (uint32_t)((wr*64+mt*16+arow)*80 + (s*8+akq)*4);
                ldsm4(a[mt][0],a[mt][1],a[mt][2],a[mt][3],ad);
            }
            uint32_t b[2][4];
            #pragma unroll
            for(int np=0;np<2;np++){
                uint32_t bd=bbase + (uint32_t)((wc*32+np*16+brow)*80 + (s*8+bkq)*4);
                ldsm4(b[np][0],b[np][1],b[np][2],b[np][3],bd);
            }
            #pragma unroll
            for(int mt=0;mt<4;mt++)
                #pragma unroll
                for(int nt=0;nt<4;nt++)
                    mma8(acc[mt][nt], a[mt], &b[nt>>1][(nt&1)*2]);
        }
        __syncthreads();
    }

    if(epi&1){ if(t<128){ ssum[t]=0.f; ssq[t]=0.f; } __syncthreads(); }
    int b_ix=(int)(m0>>7);
    #pragma unroll
    for(int mt=0;mt<4;mt++){
        size_t row0=m0+wr*64+mt*16+gid;
        int r0l=wr*64+mt*16+gid;
        float t0=0.f,t1=0.f;
        if(epi&2){ t0=fmaxf(pt[r0l],1e-6f); t1=fmaxf(pt[r0l+8],1e-6f); }
        #pragma unroll
        for(int nt=0;nt<4;nt++){
            int cl=wc*32+nt*8+tq*2;
            float bb0=bias?bias[bcol+cl]:0.f, bb1=bias?bias[bcol+cl+1]:0.f;
            float v0=acc[mt][nt][0]+bb0, v1=acc[mt][nt][1]+bb1;
            float v2=acc[mt][nt][2]+bb0, v3=acc[mt][nt][3]+bb1;
            if(epi&2){
                float l0=eigs[(size_t)b_ix*4097*128 + cl];
                float l1=eigs[(size_t)b_ix*4097*128 + cl+1];
                v0*=__expf(-l0*t0); v1*=__expf(-l1*t0);
                v2*=__expf(-l0*t1); v3*=__expf(-l1*t1);
            }
            if(epi&4){ v0=tf32r(v0); v1=tf32r(v1); v2=tf32r(v2); v3=tf32r(v3); }
            *(float2*)&C[row0*(size_t)ldc+bcol+cl]     = make_float2(v0,v1);
            *(float2*)&C[(row0+8)*(size_t)ldc+bcol+cl] = make_float2(v2,v3);
            if(epi&1){
                atomicAdd(&ssum[cl],  v0+v2); atomicAdd(&ssq[cl],  v0*v0+v2*v2);
                atomicAdd(&ssum[cl+1],v1+v3); atomicAdd(&ssq[cl+1],v1*v1+v3*v3);
            }
        }
    }
    if(epi&1){
        __syncthreads();
        if(t<128){ atomicAdd(&g_stsum[bcol+t],ssum[t]); atomicAdd(&g_stsq[bcol+t],ssq[t]); }
    }
}

// ---------------- msg activation + segment-sum scatter ----------------
__global__ __launch_bounds__(256) void k_msg(const int* __restrict__ nbr){
    int warp=threadIdx.x>>5, lane=threadIdx.x&31;
    size_t e=(size_t)blockIdx.x*8+warp;
    const float* h2=g_H2+e*256;
    int j=lane*4;
    float4 f=*(const float4*)(h2+j);
    float4 c=*(const float4*)(h2+128+j);
    float fr[4]={f.x,f.y,f.z,f.w}, cr[4]={c.x,c.y,c.z,c.w}, o[4];
    #pragma unroll
    for(int s=0;s<4;s++){
        int jj=j+s;
        float fv=g_affA[jj]*fr[s]+g_affC[jj];
        float cv=g_affA[128+jj]*cr[s]+g_affC[128+jj];
        float sg=1.f/(1.f+__expf(-fv));
        float sp=fmaxf(cv,0.f)+log1pf(__expf(-fabsf(cv)));
        o[s]=sg*sp;
    }
    float* dst=g_h+(size_t)nbr[e]*128+j;
    atomicAdd(dst+0,o[0]); atomicAdd(dst+1,o[1]);
    atomicAdd(dst+2,o[2]); atomicAdd(dst+3,o[3]);
}

// ---------------- h = tf32r(h + affA*y2 + affC) ----------------
__global__ void k_update(){
    size_t i=(size_t)blockIdx.x*blockDim.x+threadIdx.x;
    int j=(int)((i*4)&127);
    float4 y=((const float4*)g_y2)[i];
    float4 h=((float4*)g_h)[i];
    h.x=tf32r(h.x+g_affA[j+0]*y.x+g_affC[j+0]);
    h.y=tf32r(h.y+g_affA[j+1]*y.y+g_affC[j+1]);
    h.z=tf32r(h.z+g_affA[j+2]*y.z+g_affC[j+2]);
    h.w=tf32r(h.w+g_affA[j+3]*y.w+g_affC[j+3]);
    ((float4*)g_h)[i]=h;
}

// ---------------- final projection + mean over V ----------------
__global__ __launch_bounds__(256) void k_out(const float* __restrict__ wo2){
    __shared__ float part[8];
    int warp=threadIdx.x>>5, lane=threadIdx.x&31;
    size_t row=(size_t)blockIdx.x*8+warp;
    int j=lane*4;
    float4 y=*(const float4*)&g_y1[row*128+j];
    float4 w=*(const float4*)&wo2[j];
    float v=0.f;
    v+=siluf(g_affA[j+0]*y.x+g_affC[j+0])*w.x;
    v+=siluf(g_affA[j+1]*y.y+g_affC[j+1])*w.y;
    v+=siluf(g_affA[j+2]*y.z+g_affC[j+2])*w.z;
    v+=siluf(g_affA[j+3]*y.w+g_affC[j+3])*w.w;
    #pragma unroll
    for(int s=16;s>0;s>>=1) v+=__shfl_xor_sync(0xffffffffu,v,s);
    if(lane==0) part[warp]=v;
    __syncthreads();
    if(threadIdx.x==0){
        float s=0.f;
        #pragma unroll
        for(int q=0;q<8;q++) s+=part[q];
        atomicAdd(&g_outacc[blockIdx.x>>8],s);
    }
}
__global__ void k_final(float* out, const float* __restrict__ bo2){
    int b=threadIdx.x;
    if(b<BB) out[b]=g_outacc[b]*(1.f/(float)VV)+bo2[0];
}

// ---------------- launch ----------------
extern "C" void kernel_launch(void* const* d_in, const int* in_sizes, int n_in,
                              void* d_out, int out_size){
    const float* chem =(const float*)d_in[0];
    const int*   nbr  =(const int*)  d_in[1];
    const float* eigs =(const float*)d_in[2];
    const float* w1   =(const float*)d_in[3];
    const float* b1   =(const float*)d_in[4];
    const float* g1   =(const float*)d_in[5];
    const float* be1  =(const float*)d_in[6];
    const float* w2   =(const float*)d_in[7];
    const float* b2   =(const float*)d_in[8];
    const float* g2   =(const float*)d_in[9];
    const float* be2  =(const float*)d_in[10];
    const float* prop =(const float*)d_in[11];
    const float* pw1  =(const float*)d_in[12];
    const float* pb1  =(const float*)d_in[13];
    const float* pg1  =(const float*)d_in[14];
    const float* pbe1 =(const float*)d_in[15];
    const float* pw2  =(const float*)d_in[16];
    const float* pb2  =(const float*)d_in[17];
    const float* pg2  =(const float*)d_in[18];
    const float* pbe2 =(const float*)d_in[19];
    const float* wo1  =(const float*)d_in[20];
    const float* bo1  =(const float*)d_in[21];
    const float* go1  =(const float*)d_in[22];
    const float* beo1 =(const float*)d_in[23];
    const float* wo2  =(const float*)d_in[24];
    const float* bo2  =(const float*)d_in[25];
    (void)in_sizes; (void)n_in; (void)out_size;

    float *w1T,*w2T,*pw1T,*pw2T,*wo1T;
    cudaGetSymbolAddress((void**)&w1T,  g_w1T);
    cudaGetSymbolAddress((void**)&w2T,  g_w2T);
    cudaGetSymbolAddress((void**)&pw1T, g_pw1T);
    cudaGetSymbolAddress((void**)&pw2T, g_pw2T);
    cudaGetSymbolAddress((void**)&wo1T, g_wo1T);
    float *Y1e,*H2,*chem48,*hbase,*hprop,*y1b,*y2b,*hspec,*hbT,*einvT,*evr;
    cudaGetSymbolAddress((void**)&Y1e,  g_Y1e);
    cudaGetSymbolAddress((void**)&H2,   g_H2);
    cudaGetSymbolAddress((void**)&chem48,g_chem48);
    cudaGetSymbolAddress((void**)&hbase,g_h);
    cudaGetSymbolAddress((void**)&hprop,g_hprop);
    cudaGetSymbolAddress((void**)&y1b,  g_y1);
    cudaGetSymbolAddress((void**)&y2b,  g_y2);
    cudaGetSymbolAddress((void**)&hspec,g_hspec);
    cudaGetSymbolAddress((void**)&hbT,  g_hbT);
    cudaGetSymbolAddress((void**)&einvT,g_einvT);
    cudaGetSymbolAddress((void**)&evr,  g_evr);

    // ---- one-time prep ----
    k_wt<<<(128*48+255)/256,256>>>(w1T, w1, 47, 128, 48);
    k_wt<<<(256*128+255)/256,256>>>(w2T, w2, 128, 256, 128);
    for(int l=0;l<3;l++){
        k_wt<<<(128*256+255)/256,256>>>(pw1T+l*128*256, pw1+(size_t)l*256*128, 256, 128, 256);
        k_wt<<<(128*128+255)/256,256>>>(pw2T+l*128*128, pw2+(size_t)l*128*128, 128, 128, 128);
    }
    k_wt<<<(128*128+255)/256,256>>>(wo1T, wo1, 128, 128, 128);
    k_prep<<<EE/8,256>>>(chem);
    k_evr<<<NNODE*128/4/256,256>>>(eigs);
    k_einvT<<<dim3(64,4,64),dim3(32,8)>>>(eigs);
    k_zero_h<<<4096,1024>>>();

    // ---- chem MLP ----
    k_zero_st<<<1,256>>>();
    k_tc<<<dim3(EE/128,1),256>>>(0, chem48, 48, 0, w1T, 48,
                                 Y1e, 128, b1, 3, 1, nullptr, nullptr);
    k_fold<<<1,256>>>(128, 1.f/(float)EE, g1, be1);
    k_act<<<EE*128/4/256,256>>>(Y1e);
    k_zero_st<<<1,256>>>();
    k_tc<<<dim3(EE/128,2),256>>>(0, Y1e, 128, 0, w2T, 128,
                                 H2, 256, b2, 8, 1, nullptr, nullptr);
    k_fold<<<1,256>>>(256, 1.f/(float)EE, g2, be2);
    k_msg<<<EE/8,256>>>(nbr);

    // ---- propagation layers ----
    for(int l=0;l<3;l++){
        k_hbT<<<dim3(64,4,64),dim3(32,8)>>>();
        // hsT[b][h][k] = hbT[b](128h x 2048v) * einvT[b](128k x 2048v)^T, coeff+round
        k_tc<<<dim3(64,1),256>>>(0, hbT, 2048, 2, einvT, 2048,
                                 hspec, 128, nullptr, 128, 2|4, eigs, prop+l*128);
        // h_prop = evr(N x 128k) * hsT[b](128h x 128k)^T, round
        k_tc<<<dim3(NNODE/128,1),256>>>(0, evr, 128, 1, hspec, 128,
                                 hprop, 128, nullptr, 8, 4, nullptr, nullptr);
        k_zero_st<<<1,256>>>();
        k_tc<<<dim3(NNODE/128,1),256>>>(1, nullptr, 256, 0, pw1T+l*128*256, 256,
                                 y1b, 128, pb1+l*128, 16, 1, nullptr, nullptr);
        k_fold<<<1,256>>>(128, 1.f/(float)NNODE, pg1+l*128, pbe1+l*128);
        k_act<<<NNODE*128/4/256,256>>>(y1b);
        k_zero_st<<<1,256>>>();
        k_tc<<<dim3(NNODE/128,1),256>>>(0, y1b, 128, 0, pw2T+l*128*128, 128,
                                 y2b, 128, pb2+l*128, 8, 1, nullptr, nullptr);
        k_fold<<<1,256>>>(128, 1.f/(float)NNODE, pg2+l*128, pbe2+l*128);
        k_update<<<16384,256>>>();
    }

    // ---- output head ----
    k_zero_st<<<1,256>>>();
    k_tc<<<dim3(NNODE/128,1),256>>>(0, hbase, 128, 0, wo1T, 128,
                                 y1b, 128, bo1, 8, 1, nullptr, nullptr);
    k_fold<<<1,256>>>(128, 1.f/(float)NNODE, go1, beo1);
    k_out<<<NNODE/8,256>>>(wo2);
    k_final<<<1,64>>>((float*)d_out, bo2);
}

// round 9
// speedup vs baseline: 1.1589x; 1.1233x over previous
#include <cuda_runtime.h>
#include <cstdint>
#include <cstddef>

#define BB 64
#define VV 2048
#define HH 128
#define NNODE (BB*VV)      /* 131072 */
#define EE 1048576
#define CFD 47
#define EPSB 1e-5f

// ---------------- device scratch (allocation-free rule) ----------------
__device__ __align__(16) float g_Y1e[(size_t)EE*HH];      // 512MB  X@w1+b1 (pre-BN)
__device__ __align__(16) float g_H2[(size_t)EE*2*HH];     // 1GB    silu(BN1)@w2+b2 (pre-BN)
__device__ __align__(16) float g_h[(size_t)NNODE*HH];     // 64MB
__device__ __align__(16) float g_hprop[(size_t)NNODE*HH];
__device__ __align__(16) float g_y1[(size_t)NNODE*HH];
__device__ __align__(16) float g_y2[(size_t)NNODE*HH];
__device__ __align__(16) float g_hspec[(size_t)BB*HH*HH]; // 4MB
__device__ float g_stsum[2*HH];
__device__ float g_stsq[2*HH];
__device__ float g_affA[2*HH];
__device__ float g_affC[2*HH];
__device__ float g_outacc[BB];

__device__ __forceinline__ float siluf(float x){ return x/(1.f+__expf(-x)); }

// ---- packed fp32x2 FMA (Blackwell FFMA2; ptxas never auto-emits this) ----
__device__ __forceinline__ void ffma2(uint64_t& c, uint64_t a, uint64_t b){
    asm("fma.rn.f32x2 %0, %1, %2, %0;" : "+l"(c) : "l"(a), "l"(b));
}
__device__ __forceinline__ uint64_t dup2(float x){
    uint64_t r; asm("mov.b64 %0, {%1, %1};" : "=l"(r) : "f"(x)); return r;
}
__device__ __forceinline__ float2 unp2(uint64_t v){
    float2 f; asm("mov.b64 {%0, %1}, %2;" : "=f"(f.x), "=f"(f.y) : "l"(v)); return f;
}

// ---------------- zero kernels ----------------
__global__ void k_zero_h(){
    size_t i=(size_t)blockIdx.x*blockDim.x+threadIdx.x;
    ((float4*)g_h)[i]=make_float4(0.f,0.f,0.f,0.f);
    if(blockIdx.x==0&&threadIdx.x<BB) g_outacc[threadIdx.x]=0.f;
}
__global__ void k_zero_spec(){
    size_t i=(size_t)blockIdx.x*blockDim.x+threadIdx.x;
    ((float4*)g_hspec)[i]=make_float4(0.f,0.f,0.f,0.f);
}
__global__ void k_zero_st(){
    int t=threadIdx.x;
    if(t<2*HH){ g_stsum[t]=0.f; g_stsq[t]=0.f; }
}

// ---------------- GEMM1: Y1 = X@w1 + b1 (K=47), with column stats ----------------
__global__ __launch_bounds__(256) void k_gemm1(const float* __restrict__ X,
                                               const float* __restrict__ w1,
                                               const float* __restrict__ b1){
    __shared__ float ws[CFD*HH];    // [k][j], reused as stats scratch
    __shared__ float xs[128*48];    // padded rows
    int t=threadIdx.x, ty=t>>4, tx=t&15;
    size_t m0=(size_t)blockIdx.x*128;
    for(int i=t;i<CFD*HH;i+=256) ws[i]=w1[i];
    const float* src=X+m0*CFD;
    for(int i=t;i<128*CFD;i+=256) xs[(i/CFD)*48+(i%CFD)]=src[i];
    __syncthreads();
    uint64_t acc[8][4]={};
    for(int k=0;k<CFD;k++){
        ulonglong2 q0=*(const ulonglong2*)&ws[k*HH+tx*8];
        ulonglong2 q1=*(const ulonglong2*)&ws[k*HH+tx*8+4];
        uint64_t bp[4]={q0.x,q0.y,q1.x,q1.y};
        #pragma unroll
        for(int ri=0;ri<8;ri++){
            uint64_t ad=dup2(xs[(ty*8+ri)*48+k]);
            #pragma unroll
            for(int cp=0;cp<4;cp++) ffma2(acc[ri][cp],ad,bp[cp]);
        }
    }
    float bb[8];
    #pragma unroll
    for(int ci=0;ci<8;ci++) bb[ci]=b1[tx*8+ci];
    float ls[8]={}, lq[8]={};
    #pragma unroll
    for(int ri=0;ri<8;ri++){
        float v[8];
        #pragma unroll
        for(int cp=0;cp<4;cp++){ float2 p=unp2(acc[ri][cp]); v[2*cp]=p.x; v[2*cp+1]=p.y; }
        #pragma unroll
        for(int ci=0;ci<8;ci++){ v[ci]+=bb[ci]; ls[ci]+=v[ci]; lq[ci]+=v[ci]*v[ci]; }
        size_t row=m0+ty*8+ri;
        *(float4*)&g_Y1e[row*HH+tx*8]  =make_float4(v[0],v[1],v[2],v[3]);
        *(float4*)&g_Y1e[row*HH+tx*8+4]=make_float4(v[4],v[5],v[6],v[7]);
    }
    __syncthreads();
    #pragma unroll
    for(int ci=0;ci<8;ci++) ws[ty*128+tx*8+ci]=ls[ci];
    __syncthreads();
    if(t<128){ float s=0.f; for(int q=0;q<16;q++) s+=ws[q*128+t]; atomicAdd(&g_stsum[t],s); }
    __syncthreads();
    #pragma unroll
    for(int ci=0;ci<8;ci++) ws[ty*128+tx*8+ci]=lq[ci];
    __syncthreads();
    if(t<128){ float s=0.f; for(int q=0;q<16;q++) s+=ws[q*128+t]; atomicAdd(&g_stsq[t],s); }
}

// ---------------- fold stats -> affine ----------------
__global__ void k_fold(int ncols, float invn,
                       const float* __restrict__ g, const float* __restrict__ be){
    int j=threadIdx.x;
    if(j<ncols){
        float m=g_stsum[j]*invn;
        float var=g_stsq[j]*invn-m*m;
        float A=g[j]*rsqrtf(var+EPSB);
        g_affA[j]=A;
        g_affC[j]=be[j]-A*m;
    }
}

// ---------------- generic 128x128 tiled GEMM (FFMA2) ----------------
// mode 0: plain A           mode 1: A = concat(g_h, g_hprop), Kdim=256
// mode 2: A elem -> silu(affA*a+affC)
// mode 3: A = evecs from eigs (per-batch), B = g_hspec per-batch
// asel: 0=g_Y1e 1=g_h 2=g_y1 ; csel: 0=g_H2 1=g_hprop 2=g_y1 3=g_y2
__global__ __launch_bounds__(256) void k_mm(int mode, int asel, int csel,
        const float* __restrict__ eigs,
        const float* __restrict__ Bw, int ldb,
        const float* __restrict__ bias,
        int ldc, int Kdim, int do_stats)
{
    __shared__ float As[16*128];
    __shared__ float Bs[16*128];
    const float* A=(asel==0)?g_Y1e:(asel==1)?g_h:g_y1;
    float* Cout=(csel==0)?g_H2:(csel==1)?g_hprop:(csel==2)?g_y1:g_y2;
    int t=threadIdx.x, ty=t>>4, tx=t&15;
    size_t m0=(size_t)blockIdx.x*128;
    int bcol=blockIdx.y*128;
    const float* Abase=A;
    const float* Bbase=Bw;
    if(mode==3){
        size_t b=m0>>11;
        Abase=eigs+(b*4097+1)*128+(m0&2047)*128;
        Bbase=g_hspec+b*16384;
    }
    uint64_t acc[8][4]={};
    int am=t>>1, akq=(t&1)*8;
    int bk=t>>4, bn=(t&15)*8;
    for(int k0=0;k0<Kdim;k0+=16){
        const float* ap;
        if(mode==1) ap=(k0<128)?(g_h+(m0+am)*128+k0+akq):(g_hprop+(m0+am)*128+(k0-128)+akq);
        else if(mode==3) ap=Abase+(size_t)am*128+k0+akq;
        else ap=Abase+(m0+am)*128+k0+akq;
        float4 v0=*(const float4*)ap, v1=*(const float4*)(ap+4);
        float av[8]={v0.x,v0.y,v0.z,v0.w,v1.x,v1.y,v1.z,v1.w};
        if(mode==2){
            #pragma unroll
            for(int i=0;i<8;i++){ int kg=k0+akq+i; av[i]=siluf(g_affA[kg]*av[i]+g_affC[kg]); }
        }
        #pragma unroll
        for(int i=0;i<8;i++) As[(akq+i)*128+am]=av[i];
        const float* bp=Bbase+(size_t)(k0+bk)*ldb+bcol+bn;
        *(float4*)&Bs[bk*128+bn]  =*(const float4*)bp;
        *(float4*)&Bs[bk*128+bn+4]=*(const float4*)(bp+4);
        __syncthreads();
        #pragma unroll
        for(int kk=0;kk<16;kk++){
            float4 a0=*(const float4*)&As[kk*128+ty*8];
            float4 a1=*(const float4*)&As[kk*128+ty*8+4];
            ulonglong2 q0=*(const ulonglong2*)&Bs[kk*128+tx*8];
            ulonglong2 q1=*(const ulonglong2*)&Bs[kk*128+tx*8+4];
            uint64_t bp2[4]={q0.x,q0.y,q1.x,q1.y};
            float aa[8]={a0.x,a0.y,a0.z,a0.w,a1.x,a1.y,a1.z,a1.w};
            #pragma unroll
            for(int ri=0;ri<8;ri++){
                uint64_t ad=dup2(aa[ri]);
                #pragma unroll
                for(int cp=0;cp<4;cp++) ffma2(acc[ri][cp],ad,bp2[cp]);
            }
        }
        __syncthreads();
    }
    float bb[8];
    #pragma unroll
    for(int ci=0;ci<8;ci++) bb[ci]=bias?bias[bcol+tx*8+ci]:0.f;
    float ls[8]={}, lq[8]={};
    #pragma unroll
    for(int ri=0;ri<8;ri++){
        float v[8];
        #pragma unroll
        for(int cp=0;cp<4;cp++){ float2 p=unp2(acc[ri][cp]); v[2*cp]=p.x; v[2*cp+1]=p.y; }
        #pragma unroll
        for(int ci=0;ci<8;ci++){ v[ci]+=bb[ci]; ls[ci]+=v[ci]; lq[ci]+=v[ci]*v[ci]; }
        size_t row=m0+ty*8+ri;
        *(float4*)&Cout[row*(size_t)ldc+bcol+tx*8]  =make_float4(v[0],v[1],v[2],v[3]);
        *(float4*)&Cout[row*(size_t)ldc+bcol+tx*8+4]=make_float4(v[4],v[5],v[6],v[7]);
    }
    if(do_stats){
        __syncthreads();
        #pragma unroll
        for(int ci=0;ci<8;ci++) As[ty*128+tx*8+ci]=ls[ci];
        __syncthreads();
        if(t<128){ float s=0.f; for(int q=0;q<16;q++) s+=As[q*128+t]; atomicAdd(&g_stsum[bcol+t],s); }
        __syncthreads();
        #pragma unroll
        for(int ci=0;ci<8;ci++) As[ty*128+tx*8+ci]=lq[ci];
        __syncthreads();
        if(t<128){ float s=0.f; for(int q=0;q<16;q++) s+=As[q*128+t]; atomicAdd(&g_stsq[bcol+t],s); }
    }
}

// ---------------- msg activation + segment-sum scatter ----------------
__global__ __launch_bounds__(256) void k_msg(const int* __restrict__ nbr){
    int warp=threadIdx.x>>5, lane=threadIdx.x&31;
    size_t e=(size_t)blockIdx.x*8+warp;
    const float* h2=g_H2+e*256;
    int j=lane*4;
    float4 f=*(const float4*)(h2+j);
    float4 c=*(const float4*)(h2+128+j);
    float fr[4]={f.x,f.y,f.z,f.w}, cr[4]={c.x,c.y,c.z,c.w}, o[4];
    #pragma unroll
    for(int s=0;s<4;s++){
        int jj=j+s;
        float fv=g_affA[jj]*fr[s]+g_affC[jj];
        float cv=g_affA[128+jj]*cr[s]+g_affC[128+jj];
        float sg=1.f/(1.f+__expf(-fv));
        float sp=fmaxf(cv,0.f)+log1pf(__expf(-fabsf(cv)));
        o[s]=sg*sp;
    }
    float* dst=g_h+(size_t)nbr[e]*128+j;
    atomicAdd(dst+0,o[0]); atomicAdd(dst+1,o[1]);
    atomicAdd(dst+2,o[2]); atomicAdd(dst+3,o[3]);
}

// ---------------- h_spec (FFMA2): per-batch Einv^T @ hb, V chunked x4, atomic accumulate ----------------
__global__ __launch_bounds__(256) void k_spec(const float* __restrict__ eigs){
    __shared__ float As[16*128];
    __shared__ float Bs[16*128];
    int t=threadIdx.x, ty=t>>4, tx=t&15;
    int b=blockIdx.x>>2, c=blockIdx.x&3;
    int v0=c*512;
    const float* Abase=eigs+((size_t)b*4097+1+2048)*128;   // evecs_inv rows
    const float* Hbase=g_h+((size_t)b*2048)*128;
    int vr=t>>4, cq=(t&15)*8;
    uint64_t acc[8][4]={};
    for(int vt=0;vt<512;vt+=16){
        const float* ap=Abase+(size_t)(v0+vt+vr)*128+cq;
        *(float4*)&As[vr*128+cq]  =*(const float4*)ap;
        *(float4*)&As[vr*128+cq+4]=*(const float4*)(ap+4);
        const float* bp=Hbase+(size_t)(v0+vt+vr)*128+cq;
        *(float4*)&Bs[vr*128+cq]  =*(const float4*)bp;
        *(float4*)&Bs[vr*128+cq+4]=*(const float4*)(bp+4);
        __syncthreads();
        #pragma unroll
        for(int vv=0;vv<16;vv++){
            float4 a0=*(const float4*)&As[vv*128+ty*8];
            float4 a1=*(const float4*)&As[vv*128+ty*8+4];
            ulonglong2 q0=*(const ulonglong2*)&Bs[vv*128+tx*8];
            ulonglong2 q1=*(const ulonglong2*)&Bs[vv*128+tx*8+4];
            uint64_t bp2[4]={q0.x,q0.y,q1.x,q1.y};
            float aa[8]={a0.x,a0.y,a0.z,a0.w,a1.x,a1.y,a1.z,a1.w};
            #pragma unroll
            for(int ri=0;ri<8;ri++){
                uint64_t ad=dup2(aa[ri]);
                #pragma unroll
                for(int cp=0;cp<4;cp++) ffma2(acc[ri][cp],ad,bp2[cp]);
            }
        }
        __syncthreads();
    }
    float* dst=g_hspec+(size_t)b*16384;
    #pragma unroll
    for(int ri=0;ri<8;ri++){
        #pragma unroll
        for(int cp=0;cp<4;cp++){
            float2 p=unp2(acc[ri][cp]);
            atomicAdd(&dst[(ty*8+ri)*128+tx*8+2*cp],  p.x);
            atomicAdd(&dst[(ty*8+ri)*128+tx*8+2*cp+1],p.y);
        }
    }
}

// ---------------- h_spec *= exp(-lam*t) ----------------
__global__ void k_coeff(const float* __restrict__ eigs, const float* __restrict__ pt){
    int i=blockIdx.x*blockDim.x+threadIdx.x;   // B*128*128
    int b=i>>14, k=(i>>7)&127, hcol=i&127;
    float lam=eigs[(size_t)b*4097*128+k];
    float tt=fmaxf(pt[hcol],1e-6f);
    g_hspec[i]*=__expf(-lam*tt);
}

// ---------------- h += affA*y2 + affC ----------------
__global__ void k_update(){
    size_t i=(size_t)blockIdx.x*blockDim.x+threadIdx.x;
    int j=(int)((i*4)&127);
    float4 y=((const float4*)g_y2)[i];
    float4 h=((float4*)g_h)[i];
    h.x+=g_affA[j+0]*y.x+g_affC[j+0];
    h.y+=g_affA[j+1]*y.y+g_affC[j+1];
    h.z+=g_affA[j+2]*y.z+g_affC[j+2];
    h.w+=g_affA[j+3]*y.w+g_affC[j+3];
    ((float4*)g_h)[i]=h;
}

// ---------------- final projection + mean over V ----------------
__global__ __launch_bounds__(256) void k_out(const float* __restrict__ wo2){
    __shared__ float part[8];
    int warp=threadIdx.x>>5, lane=threadIdx.x&31;
    size_t row=(size_t)blockIdx.x*8+warp;
    int j=lane*4;
    float4 y=*(const float4*)&g_y1[row*128+j];
    float4 w=*(const float4*)&wo2[j];
    float v=0.f;
    v+=siluf(g_affA[j+0]*y.x+g_affC[j+0])*w.x;
    v+=siluf(g_affA[j+1]*y.y+g_affC[j+1])*w.y;
    v+=siluf(g_affA[j+2]*y.z+g_affC[j+2])*w.z;
    v+=siluf(g_affA[j+3]*y.w+g_affC[j+3])*w.w;
    #pragma unroll
    for(int s=16;s>0;s>>=1) v+=__shfl_xor_sync(0xffffffffu,v,s);
    if(lane==0) part[warp]=v;
    __syncthreads();
    if(threadIdx.x==0){
        float s=0.f;
        #pragma unroll
        for(int q=0;q<8;q++) s+=part[q];
        atomicAdd(&g_outacc[blockIdx.x>>8],s);   // 256 blocks per batch
    }
}

__global__ void k_final(float* out, const float* __restrict__ bo2){
    int b=threadIdx.x;
    if(b<BB) out[b]=g_outacc[b]*(1.f/(float)VV)+bo2[0];
}

// ---------------- launch ----------------
extern "C" void kernel_launch(void* const* d_in, const int* in_sizes, int n_in,
                              void* d_out, int out_size){
    const float* chem =(const float*)d_in[0];
    const int*   nbr  =(const int*)  d_in[1];
    const float* eigs =(const float*)d_in[2];
    const float* w1   =(const float*)d_in[3];
    const float* b1   =(const float*)d_in[4];
    const float* g1   =(const float*)d_in[5];
    const float* be1  =(const float*)d_in[6];
    const float* w2   =(const float*)d_in[7];
    const float* b2   =(const float*)d_in[8];
    const float* g2   =(const float*)d_in[9];
    const float* be2  =(const float*)d_in[10];
    const float* prop =(const float*)d_in[11];
    const float* pw1  =(const float*)d_in[12];
    const float* pb1  =(const float*)d_in[13];
    const float* pg1  =(const float*)d_in[14];
    const float* pbe1 =(const float*)d_in[15];
    const float* pw2  =(const float*)d_in[16];
    const float* pb2  =(const float*)d_in[17];
    const float* pg2  =(const float*)d_in[18];
    const float* pbe2 =(const float*)d_in[19];
    const float* wo1  =(const float*)d_in[20];
    const float* bo1  =(const float*)d_in[21];
    const float* go1  =(const float*)d_in[22];
    const float* beo1 =(const float*)d_in[23];
    const float* wo2  =(const float*)d_in[24];
    const float* bo2  =(const float*)d_in[25];
    (void)in_sizes; (void)n_in; (void)out_size;

    // chem MLP over E rows
    k_zero_h<<<4096,1024>>>();
    k_zero_st<<<1,256>>>();
    k_gemm1<<<EE/128,256>>>(chem,w1,b1);
    k_fold<<<1,256>>>(128,1.f/(float)EE,g1,be1);
    k_zero_st<<<1,256>>>();
    k_mm<<<dim3(EE/128,2),256>>>(2,0,0,nullptr,w2,256,b2,256,128,1);   // H2 = siluBN1(Y1)@w2+b2
    k_fold<<<1,256>>>(256,1.f/(float)EE,g2,be2);
    k_msg<<<EE/8,256>>>(nbr);                                          // h = segment_sum(msg)

    // propagation layers
    for(int l=0;l<3;l++){
        k_zero_spec<<<256,1024>>>();
        k_spec<<<256,256>>>(eigs);
        k_coeff<<<4096,256>>>(eigs,prop+l*128);
        k_mm<<<dim3(NNODE/128,1),256>>>(3,1,1,eigs,nullptr,128,nullptr,128,128,0);  // h_prop
        k_zero_st<<<1,256>>>();
        k_mm<<<dim3(NNODE/128,1),256>>>(1,1,2,nullptr,pw1+(size_t)l*256*128,128,pb1+l*128,128,256,1); // y1
        k_fold<<<1,256>>>(128,1.f/(float)NNODE,pg1+l*128,pbe1+l*128);
        k_zero_st<<<1,256>>>();
        k_mm<<<dim3(NNODE/128,1),256>>>(2,2,3,nullptr,pw2+(size_t)l*128*128,128,pb2+l*128,128,128,1); // y2
        k_fold<<<1,256>>>(128,1.f/(float)NNODE,pg2+l*128,pbe2+l*128);
        k_update<<<16384,256>>>();                                     // h += BN(y2)
    }

    // output head
    k_zero_st<<<1,256>>>();
    k_mm<<<dim3(NNODE/128,1),256>>>(0,1,2,nullptr,wo1,128,bo1,128,128,1);  // y1 = h@wo1+bo1
    k_fold<<<1,256>>>(128,1.f/(float)NNODE,go1,beo1);
    k_out<<<NNODE/8,256>>>(wo2);
    k_final<<<1,64>>>((float*)d_out,bo2);
}